// round 6
// baseline (speedup 1.0000x reference)
#include <cuda_runtime.h>
#include <cuda_fp16.h>
#include <math.h>

#define N_NODES 100000
#define N_EDGES 3200000
#define F_IN    256
#define U       32
#define C       40
#define H2S     48          // h2 row stride in halves (96B = 3 sectors)

#define SCAN_CH   512
#define SCAN_NB   ((N_NODES + SCAN_CH - 1) / SCAN_CH)   // 196

// ---- scratch (device globals; no allocations allowed) ----
__device__ int    g_degout_i[N_NODES];
__device__ int    g_degin_i[N_NODES];
__device__ float  g_invout[N_NODES];
__device__ float  g_invin[N_NODES];
__device__ int    g_part[SCAN_NB];
__device__ int    g_off[N_NODES + 1];
__device__ int    g_cursor[N_NODES];
__device__ int    g_esrc[N_EDGES];
__device__ __half g_h1h[(size_t)N_NODES * U];    // fp16 layer-1 messages (64B rows)
__device__ float  g_h1r[(size_t)N_NODES * U];    // relu(layer-1 out), fp32
__device__ __half g_h2h[(size_t)N_NODES * H2S];  // fp16 layer-2 messages (96B rows)

// ---- packed f32x2 helpers ----
__device__ __forceinline__ unsigned long long pack2(float x, float y) {
    unsigned long long r;
    asm("mov.b64 %0, {%1, %2};" : "=l"(r) : "f"(x), "f"(y));
    return r;
}
__device__ __forceinline__ void unpack2(unsigned long long v, float& x, float& y) {
    asm("mov.b64 {%0, %1}, %2;" : "=f"(x), "=f"(y) : "l"(v));
}
__device__ __forceinline__ void ffma2(unsigned long long& d,
                                      unsigned long long a, unsigned long long b) {
    asm("fma.rn.f32x2 %0, %1, %2, %3;" : "=l"(d) : "l"(a), "l"(b), "l"(d));
}

// ---------------------------------------------------------------------------
__global__ void zero_deg_kernel() {
    int i = blockIdx.x * blockDim.x + threadIdx.x;
    if (i < N_NODES) { g_degout_i[i] = 0; g_degin_i[i] = 0; }
}

__global__ void hist_kernel(const int* __restrict__ src, const int* __restrict__ dst) {
    int e = blockIdx.x * blockDim.x + threadIdx.x;
    if (e >= N_EDGES) return;
    atomicAdd(&g_degout_i[src[e]], 1);
    atomicAdd(&g_degin_i[dst[e]], 1);
}

__global__ void invsqrt_kernel() {
    int n = blockIdx.x * blockDim.x + threadIdx.x;
    if (n >= N_NODES) return;
    g_invout[n] = rsqrtf(fmaxf((float)g_degout_i[n], 1.0f));
    g_invin[n]  = rsqrtf(fmaxf((float)g_degin_i[n],  1.0f));
}

// ---------------------------------------------------------------------------
__global__ void __launch_bounds__(SCAN_CH) scan_part_kernel() {
    __shared__ int sw[SCAN_CH / 32];
    const int t = threadIdx.x;
    const int i = blockIdx.x * SCAN_CH + t;
    int v = (i < N_NODES) ? g_degin_i[i] : 0;
#pragma unroll
    for (int o = 16; o; o >>= 1) v += __shfl_xor_sync(0xffffffffu, v, o);
    if ((t & 31) == 0) sw[t >> 5] = v;
    __syncthreads();
    if (t < SCAN_CH / 32) {
        int s = sw[t];
#pragma unroll
        for (int o = SCAN_CH / 64; o; o >>= 1) s += __shfl_xor_sync(0xffffffffu, s, o);
        if (t == 0) g_part[blockIdx.x] = s;
    }
}

__global__ void scan_mid_kernel() {
    __shared__ int s[256];
    const int t = threadIdx.x;
    int v = (t < SCAN_NB) ? g_part[t] : 0;
    s[t] = v;
    __syncthreads();
#pragma unroll
    for (int off = 1; off < 256; off <<= 1) {
        int u = (t >= off) ? s[t - off] : 0;
        __syncthreads();
        s[t] += u;
        __syncthreads();
    }
    if (t < SCAN_NB) g_part[t] = s[t] - v;
}

__global__ void __launch_bounds__(SCAN_CH) scan_write_kernel() {
    __shared__ int s[SCAN_CH];
    const int t = threadIdx.x;
    const int i = blockIdx.x * SCAN_CH + t;
    int v = (i < N_NODES) ? g_degin_i[i] : 0;
    s[t] = v;
    __syncthreads();
#pragma unroll
    for (int off = 1; off < SCAN_CH; off <<= 1) {
        int u = (t >= off) ? s[t - off] : 0;
        __syncthreads();
        s[t] += u;
        __syncthreads();
    }
    if (i < N_NODES) {
        int off = g_part[blockIdx.x] + s[t] - v;
        g_off[i] = off;
        g_cursor[i] = off;
    }
    if (i == 0) g_off[N_NODES] = N_EDGES;
}

__global__ void reorder_kernel(const int* __restrict__ src, const int* __restrict__ dst) {
    int e = blockIdx.x * blockDim.x + threadIdx.x;
    if (e >= N_EDGES) return;
    int pos = atomicAdd(&g_cursor[dst[e]], 1);
    g_esrc[pos] = src[e];
}

// ---------------------------------------------------------------------------
// GEMM1: h1[n,u] = invout[n] * sum_k x[n,k]*W1[k,u]  -> fp16 output
// 64-node x 32-u tile, 128 threads, 4x4 per thread, packed f32x2 FMA.
#define TILE_N 64
#define KT     64
__global__ void __launch_bounds__(128) gemm1_kernel(const float* __restrict__ x,
                                                    const float* __restrict__ W1) {
    __shared__ float sX[TILE_N][KT + 1];
    __shared__ float sW[KT][U];

    const int t  = threadIdx.x;
    const int ug = t & 7;
    const int ng = t >> 3;
    const int n0 = blockIdx.x * TILE_N;

    unsigned long long acc[4][2];
#pragma unroll
    for (int i = 0; i < 4; i++) { acc[i][0] = 0ull; acc[i][1] = 0ull; }

    for (int k0 = 0; k0 < F_IN; k0 += KT) {
        for (int i = t; i < KT * U; i += 128)
            ((float*)sW)[i] = W1[k0 * U + i];
        for (int i = t; i < TILE_N * KT; i += 128) {
            int n = i >> 6;
            int k = i & (KT - 1);
            int gn = n0 + n;
            sX[n][k] = (gn < N_NODES) ? x[(size_t)gn * F_IN + k0 + k] : 0.f;
        }
        __syncthreads();
#pragma unroll 8
        for (int k = 0; k < KT; k++) {
            float4 w = *(const float4*)&sW[k][ug * 4];
            unsigned long long w01 = pack2(w.x, w.y);
            unsigned long long w23 = pack2(w.z, w.w);
#pragma unroll
            for (int i = 0; i < 4; i++) {
                float xv = sX[ng * 4 + i][k];
                unsigned long long xx = pack2(xv, xv);
                ffma2(acc[i][0], xx, w01);
                ffma2(acc[i][1], xx, w23);
            }
        }
        __syncthreads();
    }

#pragma unroll
    for (int i = 0; i < 4; i++) {
        int n = n0 + ng * 4 + i;
        if (n < N_NODES) {
            float s = g_invout[n];
            float a, b, c, d;
            unpack2(acc[i][0], a, b);
            unpack2(acc[i][1], c, d);
            __half2* dst = (__half2*)&g_h1h[(size_t)n * U + ug * 4];
            dst[0] = __floats2half2_rn(a * s, b * s);
            dst[1] = __floats2half2_rn(c * s, d * s);
        }
    }
}

// ---------------------------------------------------------------------------
// Aggregation layer 1: fp16 gather, 2 edges per warp-iteration.
// lane = 16*half + sub ; sub = feature pair (2*sub, 2*sub+1); half = edge slot.
__global__ void agg1_kernel(const float* __restrict__ b1) {
    const int n = (blockIdx.x * blockDim.x + threadIdx.x) >> 5;
    const int lane = threadIdx.x & 31;
    if (n >= N_NODES) return;
    const int half = lane >> 4;
    const int sub  = lane & 15;
    const int start = g_off[n], end = g_off[n + 1];

    float ax = 0.f, ay = 0.f;
    int e = start;
    while (e + 32 <= end) {
        int sv = g_esrc[e + lane];
#pragma unroll
        for (int i = 0; i < 16; i++) {
            int s = __shfl_sync(0xffffffffu, sv, 2 * i + half);
            __half2 v = *(const __half2*)&g_h1h[(size_t)s * U + 2 * sub];
            float2 vf = __half22float2(v);
            ax += vf.x; ay += vf.y;
        }
        e += 32;
    }
    if (e < end) {
        int rem = end - e;
        int sv = (lane < rem) ? g_esrc[e + lane] : 0;
        for (int i = 0; i < rem; i++) {
            int s = __shfl_sync(0xffffffffu, sv, i);
            if (half == 0) {   // lanes 0-15 cover all 16 feature pairs
                __half2 v = *(const __half2*)&g_h1h[(size_t)s * U + 2 * sub];
                float2 vf = __half22float2(v);
                ax += vf.x; ay += vf.y;
            }
        }
    }
    // combine the two edge-slot halves
    ax += __shfl_xor_sync(0xffffffffu, ax, 16);
    ay += __shfl_xor_sync(0xffffffffu, ay, 16);

    if (half == 0) {
        const float inv = g_invin[n];
        float2 o;
        o.x = fmaxf(ax * inv + b1[2 * sub],     0.f);
        o.y = fmaxf(ay * inv + b1[2 * sub + 1], 0.f);
        *(float2*)&g_h1r[(size_t)n * U + 2 * sub] = o;
    }
}

// ---------------------------------------------------------------------------
// GEMM2: h2[n,j] = invout[n] * sum_k h1r[n,k]*W2[k,j]  -> fp16, stride H2S
__global__ void __launch_bounds__(256) gemm2_kernel(const float* __restrict__ W2) {
    __shared__ float sH[32][U + 1];
    __shared__ float sW2[U * C];
    const int t = threadIdx.x;
    const int n0 = blockIdx.x * 32;

    for (int i = t; i < U * C; i += 256) sW2[i] = W2[i];
    for (int i = t; i < 32 * U; i += 256) {
        int n = i >> 5, k = i & 31;
        sH[n][k] = g_h1r[(size_t)(n0 + n) * U + k];
    }
    __syncthreads();

    const int n = t & 31;
    const int j0 = (t >> 5) * 5;
    float acc[5] = {};
#pragma unroll
    for (int k = 0; k < U; k++) {
        float xv = sH[n][k];
#pragma unroll
        for (int j = 0; j < 5; j++) acc[j] += xv * sW2[k * C + j0 + j];
    }
    const float s = g_invout[n0 + n];
#pragma unroll
    for (int j = 0; j < 5; j++)
        g_h2h[(size_t)(n0 + n) * H2S + j0 + j] = __float2half_rn(acc[j] * s);
}

// ---------------------------------------------------------------------------
// Aggregation layer 2: fp16 gather (lanes 0-19, half2 = feature pair)
// + norm + bias + log_softmax, fused -> d_out.
__global__ void agg2_kernel(float* __restrict__ out, const float* __restrict__ b2) {
    const int n = (blockIdx.x * blockDim.x + threadIdx.x) >> 5;
    const int lane = threadIdx.x & 31;
    if (n >= N_NODES) return;
    const int start = g_off[n], end = g_off[n + 1];
    const bool act = lane < 20;

    float ax = 0.f, ay = 0.f;
    int e = start;
    while (e + 32 <= end) {
        int sv = g_esrc[e + lane];
#pragma unroll
        for (int i = 0; i < 32; i++) {
            int s = __shfl_sync(0xffffffffu, sv, i);
            if (act) {
                __half2 v = *(const __half2*)&g_h2h[(size_t)s * H2S + 2 * lane];
                float2 vf = __half22float2(v);
                ax += vf.x; ay += vf.y;
            }
        }
        e += 32;
    }
    if (e < end) {
        int rem = end - e;
        int sv = (lane < rem) ? g_esrc[e + lane] : 0;
        for (int i = 0; i < rem; i++) {
            int s = __shfl_sync(0xffffffffu, sv, i);
            if (act) {
                __half2 v = *(const __half2*)&g_h2h[(size_t)s * H2S + 2 * lane];
                float2 vf = __half22float2(v);
                ax += vf.x; ay += vf.y;
            }
        }
    }

    const float inv = g_invin[n];
    const float NEG_INF = __int_as_float(0xff800000);
    float v0 = act ? (ax * inv + b2[2 * lane])     : NEG_INF;
    float v1 = act ? (ay * inv + b2[2 * lane + 1]) : NEG_INF;

    float m = fmaxf(v0, v1);
#pragma unroll
    for (int o = 16; o; o >>= 1) m = fmaxf(m, __shfl_xor_sync(0xffffffffu, m, o));
    float se = act ? (expf(v0 - m) + expf(v1 - m)) : 0.f;
#pragma unroll
    for (int o = 16; o; o >>= 1) se += __shfl_xor_sync(0xffffffffu, se, o);
    const float ls = logf(se);

    if (act) {
        float2 o;
        o.x = v0 - m - ls;
        o.y = v1 - m - ls;
        *(float2*)&out[(size_t)n * C + 2 * lane] = o;
    }
}

// ---------------------------------------------------------------------------
extern "C" void kernel_launch(void* const* d_in, const int* in_sizes, int n_in,
                              void* d_out, int out_size) {
    const float* x   = (const float*)d_in[0];
    const float* W1  = (const float*)d_in[1];
    const float* b1  = (const float*)d_in[2];
    const float* W2  = (const float*)d_in[3];
    const float* b2  = (const float*)d_in[4];
    const int*   src = (const int*)d_in[5];
    const int*   dst = (const int*)d_in[6];
    float* out = (float*)d_out;

    zero_deg_kernel<<<(N_NODES + 255) / 256, 256>>>();
    hist_kernel<<<(N_EDGES + 255) / 256, 256>>>(src, dst);
    invsqrt_kernel<<<(N_NODES + 255) / 256, 256>>>();
    scan_part_kernel<<<SCAN_NB, SCAN_CH>>>();
    scan_mid_kernel<<<1, 256>>>();
    scan_write_kernel<<<SCAN_NB, SCAN_CH>>>();
    reorder_kernel<<<(N_EDGES + 255) / 256, 256>>>(src, dst);
    gemm1_kernel<<<(N_NODES + TILE_N - 1) / TILE_N, 128>>>(x, W1);
    agg1_kernel<<<(N_NODES * 32 + 255) / 256, 256>>>(b1);
    gemm2_kernel<<<N_NODES / 32, 256>>>(W2);
    agg2_kernel<<<(N_NODES * 32 + 255) / 256, 256>>>(out, b2);
}

// round 7
// speedup vs baseline: 1.0899x; 1.0899x over previous
#include <cuda_runtime.h>
#include <cuda_fp16.h>
#include <math.h>

#define N_NODES 100000
#define N_EDGES 3200000
#define F_IN    256
#define U       32
#define C       40
#define H2S     48          // h2 row stride in halves (96B = 3 aligned sectors)

#define SCAN_CH   512
#define SCAN_NB   ((N_NODES + SCAN_CH - 1) / SCAN_CH)   // 196

// ---- scratch (device globals; no allocations allowed) ----
__device__ int    g_degout_i[N_NODES];
__device__ int    g_degin_i[N_NODES];
__device__ float  g_invout[N_NODES];
__device__ float  g_invin[N_NODES];
__device__ int    g_part[SCAN_NB];
__device__ int    g_off[N_NODES + 1];
__device__ int    g_cursor[N_NODES];
__device__ int    g_esrc[N_EDGES];
__device__ __align__(256) __half g_h1h[(size_t)N_NODES * U];    // fp16 L1 messages, 64B rows
__device__ float  g_h1r[(size_t)N_NODES * U];                   // relu(layer-1 out), fp32
__device__ __align__(256) __half g_h2h[(size_t)N_NODES * H2S];  // fp16 L2 messages, 96B rows

// ---------------------------------------------------------------------------
__global__ void zero_deg_kernel() {
    int i = blockIdx.x * blockDim.x + threadIdx.x;
    if (i < N_NODES) { g_degout_i[i] = 0; g_degin_i[i] = 0; }
}

__global__ void hist_kernel(const int* __restrict__ src, const int* __restrict__ dst) {
    int e = blockIdx.x * blockDim.x + threadIdx.x;
    if (e >= N_EDGES) return;
    atomicAdd(&g_degout_i[src[e]], 1);
    atomicAdd(&g_degin_i[dst[e]], 1);
}

__global__ void invsqrt_kernel() {
    int n = blockIdx.x * blockDim.x + threadIdx.x;
    if (n >= N_NODES) return;
    g_invout[n] = rsqrtf(fmaxf((float)g_degout_i[n], 1.0f));
    g_invin[n]  = rsqrtf(fmaxf((float)g_degin_i[n],  1.0f));
}

// ---------------------------------------------------------------------------
__global__ void __launch_bounds__(SCAN_CH) scan_part_kernel() {
    __shared__ int sw[SCAN_CH / 32];
    const int t = threadIdx.x;
    const int i = blockIdx.x * SCAN_CH + t;
    int v = (i < N_NODES) ? g_degin_i[i] : 0;
#pragma unroll
    for (int o = 16; o; o >>= 1) v += __shfl_xor_sync(0xffffffffu, v, o);
    if ((t & 31) == 0) sw[t >> 5] = v;
    __syncthreads();
    if (t < SCAN_CH / 32) {
        int s = sw[t];
#pragma unroll
        for (int o = SCAN_CH / 64; o; o >>= 1) s += __shfl_xor_sync(0xffffffffu, s, o);
        if (t == 0) g_part[blockIdx.x] = s;
    }
}

__global__ void scan_mid_kernel() {
    __shared__ int s[256];
    const int t = threadIdx.x;
    int v = (t < SCAN_NB) ? g_part[t] : 0;
    s[t] = v;
    __syncthreads();
#pragma unroll
    for (int off = 1; off < 256; off <<= 1) {
        int u = (t >= off) ? s[t - off] : 0;
        __syncthreads();
        s[t] += u;
        __syncthreads();
    }
    if (t < SCAN_NB) g_part[t] = s[t] - v;
}

__global__ void __launch_bounds__(SCAN_CH) scan_write_kernel() {
    __shared__ int s[SCAN_CH];
    const int t = threadIdx.x;
    const int i = blockIdx.x * SCAN_CH + t;
    int v = (i < N_NODES) ? g_degin_i[i] : 0;
    s[t] = v;
    __syncthreads();
#pragma unroll
    for (int off = 1; off < SCAN_CH; off <<= 1) {
        int u = (t >= off) ? s[t - off] : 0;
        __syncthreads();
        s[t] += u;
        __syncthreads();
    }
    if (i < N_NODES) {
        int off = g_part[blockIdx.x] + s[t] - v;
        g_off[i] = off;
        g_cursor[i] = off;
    }
    if (i == 0) g_off[N_NODES] = N_EDGES;
}

__global__ void reorder_kernel(const int* __restrict__ src, const int* __restrict__ dst) {
    int e = blockIdx.x * blockDim.x + threadIdx.x;
    if (e >= N_EDGES) return;
    int pos = atomicAdd(&g_cursor[dst[e]], 1);
    g_esrc[pos] = src[e];
}

// ---------------------------------------------------------------------------
// GEMM1: h1[n,u] = invout[n] * sum_k x[n,k]*W1[k,u]  (fp32 math, fp16 store)
#define TILE_N 64
#define KT     64
__global__ void __launch_bounds__(128) gemm1_kernel(const float* __restrict__ x,
                                                    const float* __restrict__ W1) {
    __shared__ float sX[TILE_N][KT + 1];
    __shared__ float sW[KT][U];

    const int t  = threadIdx.x;
    const int ug = t & 7;
    const int ng = t >> 3;
    const int n0 = blockIdx.x * TILE_N;

    float acc[4][4] = {};

    for (int k0 = 0; k0 < F_IN; k0 += KT) {
        for (int i = t; i < KT * U; i += 128)
            ((float*)sW)[i] = W1[k0 * U + i];
        for (int i = t; i < TILE_N * KT; i += 128) {
            int n = i >> 6;
            int k = i & (KT - 1);
            int gn = n0 + n;
            sX[n][k] = (gn < N_NODES) ? x[(size_t)gn * F_IN + k0 + k] : 0.f;
        }
        __syncthreads();
#pragma unroll
        for (int k = 0; k < KT; k++) {
            float4 w = *(const float4*)&sW[k][ug * 4];
            float xv0 = sX[ng * 4 + 0][k];
            float xv1 = sX[ng * 4 + 1][k];
            float xv2 = sX[ng * 4 + 2][k];
            float xv3 = sX[ng * 4 + 3][k];
            acc[0][0] += xv0 * w.x; acc[0][1] += xv0 * w.y; acc[0][2] += xv0 * w.z; acc[0][3] += xv0 * w.w;
            acc[1][0] += xv1 * w.x; acc[1][1] += xv1 * w.y; acc[1][2] += xv1 * w.z; acc[1][3] += xv1 * w.w;
            acc[2][0] += xv2 * w.x; acc[2][1] += xv2 * w.y; acc[2][2] += xv2 * w.z; acc[2][3] += xv2 * w.w;
            acc[3][0] += xv3 * w.x; acc[3][1] += xv3 * w.y; acc[3][2] += xv3 * w.z; acc[3][3] += xv3 * w.w;
        }
        __syncthreads();
    }

#pragma unroll
    for (int i = 0; i < 4; i++) {
        int n = n0 + ng * 4 + i;
        if (n < N_NODES) {
            float s = g_invout[n];
            __half2 h0 = __floats2half2_rn(acc[i][0] * s, acc[i][1] * s);
            __half2 h1 = __floats2half2_rn(acc[i][2] * s, acc[i][3] * s);
            __half2* dst = (__half2*)&g_h1h[(size_t)n * U + ug * 4];
            dst[0] = h0;
            dst[1] = h1;
        }
    }
}

// ---------------------------------------------------------------------------
// Aggregation layer 1 (gather over CSR, fp16 rows) + norm + bias + relu.
// One warp per node; lane = feature. Same structure as the 322µs version;
// only the load width changed (LDG.U16 instead of LDG.32).
__global__ void agg1_kernel(const float* __restrict__ b1) {
    const int n = (blockIdx.x * blockDim.x + threadIdx.x) >> 5;
    const int lane = threadIdx.x & 31;
    if (n >= N_NODES) return;
    const int start = g_off[n], end = g_off[n + 1];

    float acc = 0.f;
    int e = start;
    while (e + 32 <= end) {
        int sv = g_esrc[e + lane];
        float a0 = 0.f, a1 = 0.f, a2 = 0.f, a3 = 0.f;
#pragma unroll
        for (int i = 0; i < 32; i += 4) {
            int s0 = __shfl_sync(0xffffffffu, sv, i);
            int s1 = __shfl_sync(0xffffffffu, sv, i + 1);
            int s2 = __shfl_sync(0xffffffffu, sv, i + 2);
            int s3 = __shfl_sync(0xffffffffu, sv, i + 3);
            a0 += __half2float(g_h1h[(size_t)s0 * U + lane]);
            a1 += __half2float(g_h1h[(size_t)s1 * U + lane]);
            a2 += __half2float(g_h1h[(size_t)s2 * U + lane]);
            a3 += __half2float(g_h1h[(size_t)s3 * U + lane]);
        }
        acc += (a0 + a1) + (a2 + a3);
        e += 32;
    }
    if (e < end) {
        int rem = end - e;
        int sv = (lane < rem) ? g_esrc[e + lane] : 0;
        for (int i = 0; i < rem; i++) {
            int s = __shfl_sync(0xffffffffu, sv, i);
            acc += __half2float(g_h1h[(size_t)s * U + lane]);
        }
    }
    g_h1r[(size_t)n * U + lane] = fmaxf(acc * g_invin[n] + b1[lane], 0.f);
}

// ---------------------------------------------------------------------------
// GEMM2: h2[n,j] = invout[n] * sum_k h1r[n,k]*W2[k,j]  -> fp16, stride H2S
__global__ void __launch_bounds__(256) gemm2_kernel(const float* __restrict__ W2) {
    __shared__ float sH[32][U + 1];
    __shared__ float sW2[U * C];
    const int t = threadIdx.x;
    const int n0 = blockIdx.x * 32;

    for (int i = t; i < U * C; i += 256) sW2[i] = W2[i];
    for (int i = t; i < 32 * U; i += 256) {
        int n = i >> 5, k = i & 31;
        sH[n][k] = g_h1r[(size_t)(n0 + n) * U + k];
    }
    __syncthreads();

    const int n = t & 31;
    const int j0 = (t >> 5) * 5;
    float acc[5] = {};
#pragma unroll
    for (int k = 0; k < U; k++) {
        float xv = sH[n][k];
#pragma unroll
        for (int j = 0; j < 5; j++) acc[j] += xv * sW2[k * C + j0 + j];
    }
    const float s = g_invout[n0 + n];
#pragma unroll
    for (int j = 0; j < 5; j++)
        g_h2h[(size_t)(n0 + n) * H2S + j0 + j] = __float2half_rn(acc[j] * s);
}

// ---------------------------------------------------------------------------
// Aggregation layer 2 (gather, fp16 rows) + norm + bias + log_softmax -> d_out.
// Same structure as the 322µs version; loads are LDG.U16.
__global__ void agg2_kernel(float* __restrict__ out, const float* __restrict__ b2) {
    const int n = (blockIdx.x * blockDim.x + threadIdx.x) >> 5;
    const int lane = threadIdx.x & 31;
    if (n >= N_NODES) return;
    const int start = g_off[n], end = g_off[n + 1];

    float acc0 = 0.f, acc1 = 0.f;
    int e = start;
    while (e + 32 <= end) {
        int sv = g_esrc[e + lane];
#pragma unroll
        for (int i = 0; i < 32; i++) {
            int s = __shfl_sync(0xffffffffu, sv, i);
            acc0 += __half2float(g_h2h[(size_t)s * H2S + lane]);
            if (lane < 8) acc1 += __half2float(g_h2h[(size_t)s * H2S + 32 + lane]);
        }
        e += 32;
    }
    if (e < end) {
        int rem = end - e;
        int sv = (lane < rem) ? g_esrc[e + lane] : 0;
        for (int i = 0; i < rem; i++) {
            int s = __shfl_sync(0xffffffffu, sv, i);
            acc0 += __half2float(g_h2h[(size_t)s * H2S + lane]);
            if (lane < 8) acc1 += __half2float(g_h2h[(size_t)s * H2S + 32 + lane]);
        }
    }

    const float inv = g_invin[n];
    const float NEG_INF = __int_as_float(0xff800000);
    float v0 = acc0 * inv + b2[lane];
    float v1 = (lane < 8) ? (acc1 * inv + b2[32 + lane]) : NEG_INF;

    float m = fmaxf(v0, v1);
#pragma unroll
    for (int o = 16; o; o >>= 1) m = fmaxf(m, __shfl_xor_sync(0xffffffffu, m, o));
    float se = expf(v0 - m) + ((lane < 8) ? expf(v1 - m) : 0.f);
#pragma unroll
    for (int o = 16; o; o >>= 1) se += __shfl_xor_sync(0xffffffffu, se, o);
    const float ls = logf(se);

    float* row = out + (size_t)n * C;
    row[lane] = v0 - m - ls;
    if (lane < 8) row[32 + lane] = v1 - m - ls;
}

// ---------------------------------------------------------------------------
extern "C" void kernel_launch(void* const* d_in, const int* in_sizes, int n_in,
                              void* d_out, int out_size) {
    const float* x   = (const float*)d_in[0];
    const float* W1  = (const float*)d_in[1];
    const float* b1  = (const float*)d_in[2];
    const float* W2  = (const float*)d_in[3];
    const float* b2  = (const float*)d_in[4];
    const int*   src = (const int*)d_in[5];
    const int*   dst = (const int*)d_in[6];
    float* out = (float*)d_out;

    zero_deg_kernel<<<(N_NODES + 255) / 256, 256>>>();
    hist_kernel<<<(N_EDGES + 255) / 256, 256>>>(src, dst);
    invsqrt_kernel<<<(N_NODES + 255) / 256, 256>>>();
    scan_part_kernel<<<SCAN_NB, SCAN_CH>>>();
    scan_mid_kernel<<<1, 256>>>();
    scan_write_kernel<<<SCAN_NB, SCAN_CH>>>();
    reorder_kernel<<<(N_EDGES + 255) / 256, 256>>>(src, dst);
    gemm1_kernel<<<(N_NODES + TILE_N - 1) / TILE_N, 128>>>(x, W1);
    agg1_kernel<<<(N_NODES * 32 + 255) / 256, 256>>>(b1);
    gemm2_kernel<<<N_NODES / 32, 256>>>(W2);
    agg2_kernel<<<(N_NODES * 32 + 255) / 256, 256>>>(out, b2);
}

// round 8
// speedup vs baseline: 1.1566x; 1.0612x over previous
#include <cuda_runtime.h>
#include <math.h>

#define N_NODES 100000
#define N_EDGES 3200000
#define F_IN    256
#define U       32
#define C       40

#define SCAN_CH   512
#define SCAN_NB   ((N_NODES + SCAN_CH - 1) / SCAN_CH)   // 196

// ---- scratch (device globals; no allocations allowed) ----
__device__ int   g_degout_i[N_NODES];
__device__ int   g_degin_i[N_NODES];
__device__ float g_invout[N_NODES];
__device__ float g_invin[N_NODES];
__device__ int   g_part[SCAN_NB];
__device__ int   g_off[N_NODES + 1];
__device__ int   g_cursor[N_NODES];
__device__ int   g_esrc[N_EDGES];
__device__ float g_h1[(size_t)N_NODES * U];   // (x * d_out^-1/2) @ W1
__device__ float g_h2[(size_t)N_NODES * C];   // (relu(L1 out) * d_out^-1/2) @ W2

// ---------------------------------------------------------------------------
__global__ void zero_deg_kernel() {
    int i = blockIdx.x * blockDim.x + threadIdx.x;
    if (i < N_NODES) { g_degout_i[i] = 0; g_degin_i[i] = 0; }
}

__global__ void hist_kernel(const int* __restrict__ src, const int* __restrict__ dst) {
    int e = blockIdx.x * blockDim.x + threadIdx.x;
    if (e >= N_EDGES) return;
    atomicAdd(&g_degout_i[src[e]], 1);
    atomicAdd(&g_degin_i[dst[e]], 1);
}

__global__ void invsqrt_kernel() {
    int n = blockIdx.x * blockDim.x + threadIdx.x;
    if (n >= N_NODES) return;
    g_invout[n] = rsqrtf(fmaxf((float)g_degout_i[n], 1.0f));
    g_invin[n]  = rsqrtf(fmaxf((float)g_degin_i[n],  1.0f));
}

// ---------------------------------------------------------------------------
// GEMM1: h1[n,u] = invout[n] * sum_k x[n,k]*W1[k,u]
// 64-node x 32-u tile, 128 threads, 4x4 per thread. (Launched as slot #4 so
// ncu captures it.)
#define TILE_N 64
#define KT     64
__global__ void __launch_bounds__(128) gemm1_kernel(const float* __restrict__ x,
                                                    const float* __restrict__ W1) {
    __shared__ float sX[TILE_N][KT + 1];
    __shared__ float sW[KT][U];

    const int t  = threadIdx.x;
    const int ug = t & 7;
    const int ng = t >> 3;
    const int n0 = blockIdx.x * TILE_N;

    float acc[4][4] = {};

    for (int k0 = 0; k0 < F_IN; k0 += KT) {
        for (int i = t; i < KT * U; i += 128)
            ((float*)sW)[i] = W1[k0 * U + i];
        for (int i = t; i < TILE_N * KT; i += 128) {
            int n = i >> 6;
            int k = i & (KT - 1);
            int gn = n0 + n;
            sX[n][k] = (gn < N_NODES) ? x[(size_t)gn * F_IN + k0 + k] : 0.f;
        }
        __syncthreads();
#pragma unroll
        for (int k = 0; k < KT; k++) {
            float4 w = *(const float4*)&sW[k][ug * 4];
            float xv0 = sX[ng * 4 + 0][k];
            float xv1 = sX[ng * 4 + 1][k];
            float xv2 = sX[ng * 4 + 2][k];
            float xv3 = sX[ng * 4 + 3][k];
            acc[0][0] += xv0 * w.x; acc[0][1] += xv0 * w.y; acc[0][2] += xv0 * w.z; acc[0][3] += xv0 * w.w;
            acc[1][0] += xv1 * w.x; acc[1][1] += xv1 * w.y; acc[1][2] += xv1 * w.z; acc[1][3] += xv1 * w.w;
            acc[2][0] += xv2 * w.x; acc[2][1] += xv2 * w.y; acc[2][2] += xv2 * w.z; acc[2][3] += xv2 * w.w;
            acc[3][0] += xv3 * w.x; acc[3][1] += xv3 * w.y; acc[3][2] += xv3 * w.z; acc[3][3] += xv3 * w.w;
        }
        __syncthreads();
    }

#pragma unroll
    for (int i = 0; i < 4; i++) {
        int n = n0 + ng * 4 + i;
        if (n < N_NODES) {
            float s = g_invout[n];
            float4 o;
            o.x = acc[i][0] * s; o.y = acc[i][1] * s;
            o.z = acc[i][2] * s; o.w = acc[i][3] * s;
            *(float4*)&g_h1[(size_t)n * U + ug * 4] = o;
        }
    }
}

// ---------------------------------------------------------------------------
__global__ void __launch_bounds__(SCAN_CH) scan_part_kernel() {
    __shared__ int sw[SCAN_CH / 32];
    const int t = threadIdx.x;
    const int i = blockIdx.x * SCAN_CH + t;
    int v = (i < N_NODES) ? g_degin_i[i] : 0;
#pragma unroll
    for (int o = 16; o; o >>= 1) v += __shfl_xor_sync(0xffffffffu, v, o);
    if ((t & 31) == 0) sw[t >> 5] = v;
    __syncthreads();
    if (t < SCAN_CH / 32) {
        int s = sw[t];
#pragma unroll
        for (int o = SCAN_CH / 64; o; o >>= 1) s += __shfl_xor_sync(0xffffffffu, s, o);
        if (t == 0) g_part[blockIdx.x] = s;
    }
}

__global__ void scan_mid_kernel() {
    __shared__ int s[256];
    const int t = threadIdx.x;
    int v = (t < SCAN_NB) ? g_part[t] : 0;
    s[t] = v;
    __syncthreads();
#pragma unroll
    for (int off = 1; off < 256; off <<= 1) {
        int u = (t >= off) ? s[t - off] : 0;
        __syncthreads();
        s[t] += u;
        __syncthreads();
    }
    if (t < SCAN_NB) g_part[t] = s[t] - v;
}

__global__ void __launch_bounds__(SCAN_CH) scan_write_kernel() {
    __shared__ int s[SCAN_CH];
    const int t = threadIdx.x;
    const int i = blockIdx.x * SCAN_CH + t;
    int v = (i < N_NODES) ? g_degin_i[i] : 0;
    s[t] = v;
    __syncthreads();
#pragma unroll
    for (int off = 1; off < SCAN_CH; off <<= 1) {
        int u = (t >= off) ? s[t - off] : 0;
        __syncthreads();
        s[t] += u;
        __syncthreads();
    }
    if (i < N_NODES) {
        int off = g_part[blockIdx.x] + s[t] - v;
        g_off[i] = off;
        g_cursor[i] = off;
    }
    if (i == 0) g_off[N_NODES] = N_EDGES;
}

__global__ void reorder_kernel(const int* __restrict__ src, const int* __restrict__ dst) {
    int e = blockIdx.x * blockDim.x + threadIdx.x;
    if (e >= N_EDGES) return;
    int pos = atomicAdd(&g_cursor[dst[e]], 1);
    g_esrc[pos] = src[e];
}

// ---------------------------------------------------------------------------
// Aggregation layer 1 + relu + GEMM2, fused.
// One warp per node; lane = feature. After the gather-reduce, the warp holds
// relu(h1_agg) one value per lane and computes h2[n,:] = v @ W2 via shfl
// broadcasts against W2 in shared.
__global__ void __launch_bounds__(256) agg1_kernel(const float* __restrict__ b1,
                                                   const float* __restrict__ W2) {
    __shared__ float sW2[U * C];
    for (int i = threadIdx.x; i < U * C; i += 256) sW2[i] = W2[i];
    __syncthreads();

    const int n = (blockIdx.x * blockDim.x + threadIdx.x) >> 5;
    const int lane = threadIdx.x & 31;
    if (n >= N_NODES) return;
    const int start = g_off[n], end = g_off[n + 1];

    float acc = 0.f;
    int e = start;
    while (e + 32 <= end) {
        int sv = g_esrc[e + lane];
        float a0 = 0.f, a1 = 0.f, a2 = 0.f, a3 = 0.f;
#pragma unroll
        for (int i = 0; i < 32; i += 4) {
            int s0 = __shfl_sync(0xffffffffu, sv, i);
            int s1 = __shfl_sync(0xffffffffu, sv, i + 1);
            int s2 = __shfl_sync(0xffffffffu, sv, i + 2);
            int s3 = __shfl_sync(0xffffffffu, sv, i + 3);
            a0 += g_h1[(size_t)s0 * U + lane];
            a1 += g_h1[(size_t)s1 * U + lane];
            a2 += g_h1[(size_t)s2 * U + lane];
            a3 += g_h1[(size_t)s3 * U + lane];
        }
        acc += (a0 + a1) + (a2 + a3);
        e += 32;
    }
    if (e < end) {
        int rem = end - e;
        int sv = (lane < rem) ? g_esrc[e + lane] : 0;
        for (int i = 0; i < rem; i++) {
            int s = __shfl_sync(0xffffffffu, sv, i);
            acc += g_h1[(size_t)s * U + lane];
        }
    }

    // relu(norm + bias)
    const float v = fmaxf(acc * g_invin[n] + b1[lane], 0.f);

    // fused gemm2: h2[n,j] = invout[n] * sum_k v[k] * W2[k,j]
    float o0 = 0.f, o1 = 0.f;
#pragma unroll
    for (int k = 0; k < U; k++) {
        float h = __shfl_sync(0xffffffffu, v, k);
        o0 += h * sW2[k * C + lane];
        if (lane < 8) o1 += h * sW2[k * C + 32 + lane];
    }
    const float so = g_invout[n];
    g_h2[(size_t)n * C + lane] = o0 * so;
    if (lane < 8) g_h2[(size_t)n * C + 32 + lane] = o1 * so;
}

// ---------------------------------------------------------------------------
// Aggregation layer 2 (gather) + norm + bias + log_softmax, fused -> d_out.
__global__ void agg2_kernel(float* __restrict__ out, const float* __restrict__ b2) {
    const int n = (blockIdx.x * blockDim.x + threadIdx.x) >> 5;
    const int lane = threadIdx.x & 31;
    if (n >= N_NODES) return;
    const int start = g_off[n], end = g_off[n + 1];

    float acc0 = 0.f, acc1 = 0.f;
    int e = start;
    while (e + 32 <= end) {
        int sv = g_esrc[e + lane];
#pragma unroll
        for (int i = 0; i < 32; i++) {
            int s = __shfl_sync(0xffffffffu, sv, i);
            acc0 += g_h2[(size_t)s * C + lane];
            if (lane < 8) acc1 += g_h2[(size_t)s * C + 32 + lane];
        }
        e += 32;
    }
    if (e < end) {
        int rem = end - e;
        int sv = (lane < rem) ? g_esrc[e + lane] : 0;
        for (int i = 0; i < rem; i++) {
            int s = __shfl_sync(0xffffffffu, sv, i);
            acc0 += g_h2[(size_t)s * C + lane];
            if (lane < 8) acc1 += g_h2[(size_t)s * C + 32 + lane];
        }
    }

    const float inv = g_invin[n];
    const float NEG_INF = __int_as_float(0xff800000);
    float v0 = acc0 * inv + b2[lane];
    float v1 = (lane < 8) ? (acc1 * inv + b2[32 + lane]) : NEG_INF;

    float m = fmaxf(v0, v1);
#pragma unroll
    for (int o = 16; o; o >>= 1) m = fmaxf(m, __shfl_xor_sync(0xffffffffu, m, o));
    float se = expf(v0 - m) + ((lane < 8) ? expf(v1 - m) : 0.f);
#pragma unroll
    for (int o = 16; o; o >>= 1) se += __shfl_xor_sync(0xffffffffu, se, o);
    const float ls = logf(se);

    float* row = out + (size_t)n * C;
    row[lane] = v0 - m - ls;
    if (lane < 8) row[32 + lane] = v1 - m - ls;
}

// ---------------------------------------------------------------------------
extern "C" void kernel_launch(void* const* d_in, const int* in_sizes, int n_in,
                              void* d_out, int out_size) {
    const float* x   = (const float*)d_in[0];
    const float* W1  = (const float*)d_in[1];
    const float* b1  = (const float*)d_in[2];
    const float* W2  = (const float*)d_in[3];
    const float* b2  = (const float*)d_in[4];
    const int*   src = (const int*)d_in[5];
    const int*   dst = (const int*)d_in[6];
    float* out = (float*)d_out;

    zero_deg_kernel<<<(N_NODES + 255) / 256, 256>>>();
    hist_kernel<<<(N_EDGES + 255) / 256, 256>>>(src, dst);
    invsqrt_kernel<<<(N_NODES + 255) / 256, 256>>>();
    gemm1_kernel<<<(N_NODES + TILE_N - 1) / TILE_N, 128>>>(x, W1);   // slot #4 -> profiled
    scan_part_kernel<<<SCAN_NB, SCAN_CH>>>();
    scan_mid_kernel<<<1, 256>>>();
    scan_write_kernel<<<SCAN_NB, SCAN_CH>>>();
    reorder_kernel<<<(N_EDGES + 255) / 256, 256>>>(src, dst);
    agg1_kernel<<<(N_NODES * 32 + 255) / 256, 256>>>(b1, W2);
    agg2_kernel<<<(N_NODES * 32 + 255) / 256, 256>>>(out, b2);
}